// round 17
// baseline (speedup 1.0000x reference)
#include <cuda_runtime.h>
#include <cstdint>

#define NB 4
#define NC 19
#define NH 192
#define NW 192
#define HW (NH*NW)
#define THETA 40.0f
#define CPAD 33
#define COL_SMEM (2*192*CPAD*4)      // 50688 B dynamic smem for colK

// device scratch (no runtime allocation allowed)
__device__ float g_D     [NB*HW];    // D[b][i][j]
__device__ float g_Dt    [NB*HW];    // Dt[b][j][i] (pkZc only)
__device__ float g_Zc    [NB*HW];
__device__ float g_Zinv  [NB*HW];
__device__ float g_rowagg[NB*NC*HW];

// ---------------------------------------------------------------------------
// warp_affine_scan: full fwd+bwd line scan (192 elems, 6/lane) of
// S_i = d_i S_{i-1} + f_i and T_i = f_i + d_{i+1} T_{i+1};
// writes o_i = S_i + T_i - fk*f_i. Elements at p[i*stride].
// ---------------------------------------------------------------------------
__device__ __forceinline__ void warp_affine_scan(
    const float* d, const float* f, int stride, int lane, float fk, float* o)
{
    float dd[6], ff[6];
    #pragma unroll
    for (int e = 0; e < 6; ++e) {
        int r = lane*6 + e;
        dd[e] = d[r*stride];
        ff[e] = f[r*stride];
    }
    float a = 1.f, s = 0.f;
    #pragma unroll
    for (int e = 0; e < 6; ++e) { s = dd[e]*s + ff[e]; a *= dd[e]; }
    #pragma unroll
    for (int off = 1; off < 32; off <<= 1) {
        float pa = __shfl_up_sync(0xffffffffu, a, off);
        float pb = __shfl_up_sync(0xffffffffu, s, off);
        if (lane >= off) { s = a*pb + s; a = a*pa; }
    }
    float pre = __shfl_up_sync(0xffffffffu, s, 1);
    if (lane == 0) pre = 0.f;
    float Sv[6]; float x = pre;
    #pragma unroll
    for (int e = 0; e < 6; ++e) { x = dd[e]*x + ff[e]; Sv[e] = x; }

    // reversed-order scan for T: c'_r = d[192-r] (c'_0 = 0), b'_r = f[191-r]
    float cc[6], bb[6];
    #pragma unroll
    for (int e = 0; e < 6; ++e) {
        int r = lane*6 + e;
        cc[e] = (r == 0) ? 0.f : d[(192 - r)*stride];
        bb[e] = f[(191 - r)*stride];
    }
    float ab = 1.f, sb = 0.f;
    #pragma unroll
    for (int e = 0; e < 6; ++e) { sb = cc[e]*sb + bb[e]; ab *= cc[e]; }
    #pragma unroll
    for (int off = 1; off < 32; off <<= 1) {
        float pa = __shfl_up_sync(0xffffffffu, ab, off);
        float pb = __shfl_up_sync(0xffffffffu, sb, off);
        if (lane >= off) { sb = ab*pb + sb; ab = ab*pa; }
    }
    float preb = __shfl_up_sync(0xffffffffu, sb, 1);
    if (lane == 0) preb = 0.f;
    float Tv[6]; x = preb;
    #pragma unroll
    for (int e = 0; e < 6; ++e) { x = cc[e]*x + bb[e]; Tv[e] = x; }

    __syncwarp();   // all smem reads done before in-place writes
    #pragma unroll
    for (int e = 0; e < 6; ++e) {
        float Ti = __shfl_sync(0xffffffffu, Tv[5-e], 31 - lane);
        o[(lane*6 + e)*stride] = Sv[e] + Ti - fk*ff[e];
    }
}

// ---------------------------------------------------------------------------
// PK0: decays + tiled transpose (D and Dt, both coalesced)
__global__ void pk0_kernel(const float* __restrict__ edge) {
    __shared__ float t[32][33];
    int b  = blockIdx.z;
    int i0 = blockIdx.y * 32;
    int j0 = blockIdx.x * 32;
    int tx = threadIdx.x, ty = threadIdx.y;
    #pragma unroll
    for (int r = ty; r < 32; r += 8) {
        float e = edge[b*HW + (i0+r)*NW + j0 + tx];
        float d = __expf(-THETA * fmaxf(e, 0.f));
        g_D[b*HW + (i0+r)*NW + j0 + tx] = d;
        t[r][tx] = d;
    }
    __syncthreads();
    #pragma unroll
    for (int r = ty; r < 32; r += 8) {
        g_Dt[b*HW + (j0+r)*NW + i0 + tx] = t[tx][r];
    }
}

// pkZc: one warp per (b,j) column line (decays from Dt rows, contiguous).
// Zc[b][i][j] = S_i + T_i - 1 (ones-scan).
__global__ void pkZc_kernel() {
    int gw = (blockIdx.x * blockDim.x + threadIdx.x) >> 5;
    if (gw >= NB*NW) return;
    int lane = threadIdx.x & 31;
    int b = gw / NW, j = gw - b*NW;
    const float* dt = g_Dt + b*HW + j*NW;

    float dd[6];
    #pragma unroll
    for (int e = 0; e < 6; ++e) dd[e] = dt[lane*6 + e];
    float a = 1.f, s = 0.f;
    #pragma unroll
    for (int e = 0; e < 6; ++e) { s = dd[e]*s + 1.f; a *= dd[e]; }
    #pragma unroll
    for (int off = 1; off < 32; off <<= 1) {
        float pa = __shfl_up_sync(0xffffffffu, a, off);
        float pb = __shfl_up_sync(0xffffffffu, s, off);
        if (lane >= off) { s = a*pb + s; a = a*pa; }
    }
    float pre = __shfl_up_sync(0xffffffffu, s, 1);
    if (lane == 0) pre = 0.f;
    float Sv[6]; float x = pre;
    #pragma unroll
    for (int e = 0; e < 6; ++e) { x = dd[e]*x + 1.f; Sv[e] = x; }

    float cc[6];
    #pragma unroll
    for (int e = 0; e < 6; ++e) {
        int r = lane*6 + e;
        cc[e] = (r == 0) ? 0.f : dt[192 - r];
    }
    float ab = 1.f, sb = 0.f;
    #pragma unroll
    for (int e = 0; e < 6; ++e) { sb = cc[e]*sb + 1.f; ab *= cc[e]; }
    #pragma unroll
    for (int off = 1; off < 32; off <<= 1) {
        float pa = __shfl_up_sync(0xffffffffu, ab, off);
        float pb = __shfl_up_sync(0xffffffffu, sb, off);
        if (lane >= off) { sb = ab*pb + sb; ab = ab*pa; }
    }
    float preb = __shfl_up_sync(0xffffffffu, sb, 1);
    if (lane == 0) preb = 0.f;
    float Tv[6]; x = preb;
    #pragma unroll
    for (int e = 0; e < 6; ++e) { x = cc[e]*x + 1.f; Tv[e] = x; }

    float* zc = g_Zc + b*HW + j;
    #pragma unroll
    for (int e = 0; e < 6; ++e) {
        float Ti = __shfl_sync(0xffffffffu, Tv[5-e], 31 - lane);
        zc[(lane*6 + e)*NW] = Sv[e] + Ti - 1.f;
    }
}

// pkZr: one warp per (b,i) row line; Zinv = 1/(Zc + Zr), Zr = S + T - 2.
__global__ void pkZr_kernel() {
    int gw = (blockIdx.x * blockDim.x + threadIdx.x) >> 5;
    if (gw >= NB*NH) return;
    int lane = threadIdx.x & 31;
    int b = gw / NH, i = gw - b*NH;
    const float* dr = g_D + b*HW + i*NW;

    float dd[6];
    #pragma unroll
    for (int e = 0; e < 6; ++e) dd[e] = dr[lane*6 + e];
    float a = 1.f, s = 0.f;
    #pragma unroll
    for (int e = 0; e < 6; ++e) { s = dd[e]*s + 1.f; a *= dd[e]; }
    #pragma unroll
    for (int off = 1; off < 32; off <<= 1) {
        float pa = __shfl_up_sync(0xffffffffu, a, off);
        float pb = __shfl_up_sync(0xffffffffu, s, off);
        if (lane >= off) { s = a*pb + s; a = a*pa; }
    }
    float pre = __shfl_up_sync(0xffffffffu, s, 1);
    if (lane == 0) pre = 0.f;
    float Sv[6]; float x = pre;
    #pragma unroll
    for (int e = 0; e < 6; ++e) { x = dd[e]*x + 1.f; Sv[e] = x; }

    float cc[6];
    #pragma unroll
    for (int e = 0; e < 6; ++e) {
        int r = lane*6 + e;
        cc[e] = (r == 0) ? 0.f : dr[192 - r];
    }
    float ab = 1.f, sb = 0.f;
    #pragma unroll
    for (int e = 0; e < 6; ++e) { sb = cc[e]*sb + 1.f; ab *= cc[e]; }
    #pragma unroll
    for (int off = 1; off < 32; off <<= 1) {
        float pa = __shfl_up_sync(0xffffffffu, ab, off);
        float pb = __shfl_up_sync(0xffffffffu, sb, off);
        if (lane >= off) { sb = ab*pb + sb; ab = ab*pa; }
    }
    float preb = __shfl_up_sync(0xffffffffu, sb, 1);
    if (lane == 0) preb = 0.f;
    float Tv[6]; x = preb;
    #pragma unroll
    for (int e = 0; e < 6; ++e) { x = cc[e]*x + 1.f; Tv[e] = x; }

    const float* zc = g_Zc  + b*HW + i*NW;
    float*      zi = g_Zinv + b*HW + i*NW;
    #pragma unroll
    for (int e = 0; e < 6; ++e) {
        float Ti = __shfl_sync(0xffffffffu, Tv[5-e], 31 - lane);
        int jj = lane*6 + e;
        zi[jj] = 1.f / (zc[jj] + Sv[e] + Ti - 2.f);
    }
}

// ---------------------------------------------------------------------------
// rowK: one warp per row line (8 lines/CTA, smem-staged coalesced I/O).
// rowagg = S + T - 2f (excludes s==j).
__global__ void __launch_bounds__(256)
rowK_kernel(const float* __restrict__ feat) {
    __shared__ float sf[8*192];
    __shared__ float sd[8*192];
    int cta = blockIdx.x;
    int bc  = cta / 24, grp = cta % 24;
    int b   = bc / NC;
    int tid = threadIdx.x;

    const float* src = feat + bc*HW + grp*1536;
    const float* dsc = g_D  + b *HW + grp*1536;
    #pragma unroll
    for (int r = 0; r < 6; ++r) {
        int v = tid + r*256;
        sf[v] = src[v];
        sd[v] = dsc[v];
    }
    __syncthreads();

    int w = tid >> 5, lane = tid & 31;
    warp_affine_scan(sd + w*192, sf + w*192, 1, lane, 2.f, sf + w*192);
    __syncthreads();

    float* dst = g_rowagg + bc*HW + grp*1536;
    #pragma unroll
    for (int r = 0; r < 6; ++r) {
        int v = tid + r*256;
        dst[v] = sf[v];
    }
}

// ---------------------------------------------------------------------------
// colK: one CTA per (b,c,band) — 192 rows x 32 cols of feat staged in smem,
// column scans in-place (colagg = S + T - f), fused combine epilogue:
// fout = (colagg + rowagg) * Zinv. No transposed feat needed anywhere.
__global__ void __launch_bounds__(256)
colK_kernel(const float* __restrict__ fin, float* __restrict__ fout) {
    extern __shared__ float cs[];
    float* sf = cs;                   // [192][CPAD]
    float* sd = cs + 192*CPAD;

    int cta = blockIdx.x;
    int bc  = cta / 6, band = cta % 6;
    int b   = bc / NC;
    int j0  = band * 32;
    int tid = threadIdx.x;
    int ty  = tid >> 5, tx = tid & 31;

    const float* fsrc = fin + bc*HW + j0;
    const float* dsrc = g_D + b *HW + j0;
    #pragma unroll 4
    for (int p = 0; p < 24; ++p) {
        int r = ty + p*8;
        sf[r*CPAD + tx] = fsrc[r*NW + tx];
        sd[r*CPAD + tx] = dsrc[r*NW + tx];
    }
    __syncthreads();

    int w = ty, lane = tx;
    #pragma unroll
    for (int q = 0; q < 4; ++q) {
        int c = w*4 + q;
        warp_affine_scan(sd + c, sf + c, CPAD, lane, 1.f, sf + c);
    }
    __syncthreads();

    const float* ra = g_rowagg + bc*HW + j0;
    const float* zi = g_Zinv   + b *HW + j0;
    float*       fo = fout     + bc*HW + j0;
    #pragma unroll 4
    for (int p = 0; p < 24; ++p) {
        int r = ty + p*8;
        fo[r*NW + tx] = (sf[r*CPAD + tx] + ra[r*NW + tx]) * zi[r*NW + tx];
    }
}

// ---------------------------------------------------------------------------
extern "C" void kernel_launch(void* const* d_in, const int* in_sizes, int n_in,
                              void* d_out, int out_size) {
    const float* mask = (const float*)d_in[0];   // (4,19,192,192) fp32
    const float* edge = (const float*)d_in[1];   // (4,1,192,192)  fp32
    float* out = (float*)d_out;

    cudaFuncSetAttribute(colK_kernel,
                         cudaFuncAttributeMaxDynamicSharedMemorySize, COL_SMEM);

    dim3 g0(6, 6, NB), b0(32, 8);
    pk0_kernel<<<g0, b0>>>(edge);
    pkZc_kernel<<<(NB*NW*32 + 255)/256, 256>>>();
    pkZr_kernel<<<(NB*NH*32 + 255)/256, 256>>>();

    // iter 1 (feat = mask)
    rowK_kernel<<<NB*NC*24, 256>>>(mask);
    colK_kernel<<<NB*NC*6, 256, COL_SMEM>>>(mask, out);
    // iter 2
    rowK_kernel<<<NB*NC*24, 256>>>(out);
    colK_kernel<<<NB*NC*6, 256, COL_SMEM>>>(out, out);
    // iter 3
    rowK_kernel<<<NB*NC*24, 256>>>(out);
    colK_kernel<<<NB*NC*6, 256, COL_SMEM>>>(out, out);
}